// round 13
// baseline (speedup 1.0000x reference)
#include <cuda_runtime.h>
#include <math.h>
#include <stdint.h>

#define HIDDEN   128
#define FEATURE  264
#define N_NODES  400000
#define HEAD_OFF 39     // 4 + 5 + 30 outputs before teleport logits

#define THREADS   256
#define BM        256   // nodes per block
#define CHUNK      32   // K per staging chunk
#define WS_STRIDE 136   // 136 % 32 == 8 -> conflict-free B-fragment LDS
#define XS_STRIDE  36   // 36 % 32 == 4 -> conflict-free A-fragment LDS
#define XBUF      (BM * XS_STRIDE)   // 9216 floats per X buffer
#define NCHUNKS     4   // 128 / 32

__device__ __forceinline__ uint32_t f2tf(float x) {
    uint32_t r;
    asm("cvt.rna.tf32.f32 %0, %1;" : "=r"(r) : "f"(x));
    return r;
}

__device__ __forceinline__ void cp16(uint32_t saddr, const void* gaddr) {
    asm volatile("cp.async.cg.shared.global [%0], [%1], 16;"
                 :: "r"(saddr), "l"(gaddr));
}

// ---------------------------------------------------------------------------
// Single fused kernel, 256 threads (8 warps), R10 tiling.
//  All blocks: tf32 mma teleport GEMM for 256 nodes
//    H = relu(c + X @ W), y = H @ w2 + b2
//  W cp.async'd raw, cvt'd to tf32 in place ONCE; X register-staged with cvt
//  fused into STS -> mainloop is pure LDS + HMMA, 1 barrier per chunk.
//  Blocks 0-2: additionally run one head FFN each after the epilogue.
// ---------------------------------------------------------------------------
__global__ void __launch_bounds__(THREADS, 1) fused_kernel(
    const float* __restrict__ X,      const float* __restrict__ h_glob,
    const float* __restrict__ state,  const float* __restrict__ mask,
    const float* __restrict__ W_hl1, const float* __restrict__ b_hl1,
    const float* __restrict__ W_hl2, const float* __restrict__ b_hl2,
    const float* __restrict__ W_in1, const float* __restrict__ b_in1,
    const float* __restrict__ W_in2, const float* __restrict__ b_in2,
    const float* __restrict__ W_ex1, const float* __restrict__ b_ex1,
    const float* __restrict__ W_ex2, const float* __restrict__ b_ex2,
    const float* __restrict__ W_tp1, const float* __restrict__ b_tp1,
    const float* __restrict__ W_tp2, const float* __restrict__ b_tp2,
    float* __restrict__ out)
{
    extern __shared__ float smem[];
    float* Ws = smem;                  // 128 x 136 = 17408 floats
    float* Xs = smem + 17408;          // 2 x 9216 floats

    __shared__ float c_s[HIDDEN];
    __shared__ float cpart[2][HIDDEN];

    const int tid  = threadIdx.x;
    const int lane = tid & 31;
    const int warp = tid >> 5;       // 0..7
    const int wm   = warp & 3;       // m group (4 x 64 rows)
    const int wn   = warp >> 2;      // n group (2 x 64 cols)
    const int g    = lane >> 2;      // groupID (0..7)
    const int tg   = lane & 3;       // thread-in-group (0..3)
    const int node0 = blockIdx.x * BM;

    const uint32_t Ws_b = (uint32_t)__cvta_generic_to_shared(Ws);

    // cp.async raw W (rows 128..255 of W_tp1; 4096 float4)
    #pragma unroll
    for (int i = 0; i < 16; i++) {
        int f = tid + i * THREADS;        // 0..4095
        int row = f >> 5, q = f & 31;
        cp16(Ws_b + (row * WS_STRIDE + q * 4) * 4,
             W_tp1 + (size_t)(128 + row) * HIDDEN + q * 4);
    }
    asm volatile("cp.async.commit_group;");

    // Register-stage X chunk 0 (8 float4 per thread, coalesced)
    float4 st[8];
    #pragma unroll
    for (int i = 0; i < 8; i++) {
        int f = tid + i * THREADS;        // 0..2047
        int row = f >> 3, q = f & 7;
        size_t grow = node0 + row; if (grow >= N_NODES) grow = N_NODES - 1;
        st[i] = *(const float4*)(X + grow * HIDDEN + q * 4);
    }

    // c[j] partials (overlaps cp.async + LDG latency)
    {
        int j = tid & 127, half = tid >> 7;
        float cv = 0.0f;
        int kb = half * 64;
        #pragma unroll 8
        for (int k = kb; k < kb + 64; k++)
            cv = fmaf(h_glob[k], W_tp1[k * HIDDEN + j], cv);
        if (half) {
            #pragma unroll
            for (int k = 0; k < 8; k++)
                cv = fmaf(state[k], W_tp1[(256 + k) * HIDDEN + j], cv);
            cv += b_tp1[j];
        }
        cpart[half][j] = cv;
    }

    // STS chunk 0 with tf32 cvt
    #pragma unroll
    for (int i = 0; i < 8; i++) {
        int f = tid + i * THREADS;
        int row = f >> 3, q = f & 7;
        float* p = Xs + row * XS_STRIDE + q * 4;
        p[0] = __uint_as_float(f2tf(st[i].x));
        p[1] = __uint_as_float(f2tf(st[i].y));
        p[2] = __uint_as_float(f2tf(st[i].z));
        p[3] = __uint_as_float(f2tf(st[i].w));
    }

    asm volatile("cp.async.wait_group 0;");
    __syncthreads();

    // One-time in-place tf32 cvt of W (4352 float4); combine c partials
    {
        float4* wf = (float4*)Ws;
        #pragma unroll
        for (int i = 0; i < 17; i++) {
            float4 v = wf[tid + i * THREADS];
            v.x = __uint_as_float(f2tf(v.x)); v.y = __uint_as_float(f2tf(v.y));
            v.z = __uint_as_float(f2tf(v.z)); v.w = __uint_as_float(f2tf(v.w));
            wf[tid + i * THREADS] = v;
        }
    }
    if (tid < HIDDEN)
        c_s[tid] = cpart[0][tid] + cpart[1][tid];
    __syncthreads();

    float acc[4][8][4];
    #pragma unroll
    for (int mt = 0; mt < 4; mt++)
        #pragma unroll
        for (int nt = 0; nt < 8; nt++)
            #pragma unroll
            for (int r = 0; r < 4; r++) acc[mt][nt][r] = 0.0f;

    #pragma unroll
    for (int c = 0; c < NCHUNKS; c++) {
        // Prefetch next chunk into registers (overlaps MMA below)
        if (c < NCHUNKS - 1) {
            #pragma unroll
            for (int i = 0; i < 8; i++) {
                int f = tid + i * THREADS;
                int row = f >> 3, q = f & 7;
                size_t grow = node0 + row; if (grow >= N_NODES) grow = N_NODES - 1;
                st[i] = *(const float4*)(X + grow * HIDDEN + (c + 1) * CHUNK + q * 4);
            }
        }

        const float* buf = Xs + (c & 1) * XBUF;
        #pragma unroll
        for (int ks = 0; ks < 4; ks++) {
            int kt = c * 4 + ks;
            int col = ks * 8 + tg;
            uint32_t a[4][4];
            #pragma unroll
            for (int mt = 0; mt < 4; mt++) {
                int r0 = wm * 64 + mt * 16 + g;
                a[mt][0] = __float_as_uint(buf[r0 * XS_STRIDE + col]);
                a[mt][1] = __float_as_uint(buf[(r0 + 8) * XS_STRIDE + col]);
                a[mt][2] = __float_as_uint(buf[r0 * XS_STRIDE + col + 4]);
                a[mt][3] = __float_as_uint(buf[(r0 + 8) * XS_STRIDE + col + 4]);
            }
            // B fragments (already tf32): row = kt*8 + tg (+4), col = wn*64 + nt*8 + g
            const float* wrow = Ws + (kt * 8 + tg) * WS_STRIDE + wn * 64 + g;
            #pragma unroll
            for (int nt = 0; nt < 8; nt++) {
                uint32_t b0 = __float_as_uint(wrow[nt * 8]);
                uint32_t b1 = __float_as_uint(wrow[4 * WS_STRIDE + nt * 8]);
                #pragma unroll
                for (int mt = 0; mt < 4; mt++) {
                    asm volatile(
                        "mma.sync.aligned.m16n8k8.row.col.f32.tf32.tf32.f32 "
                        "{%0,%1,%2,%3}, {%4,%5,%6,%7}, {%8,%9}, {%0,%1,%2,%3};"
                        : "+f"(acc[mt][nt][0]), "+f"(acc[mt][nt][1]),
                          "+f"(acc[mt][nt][2]), "+f"(acc[mt][nt][3])
                        : "r"(a[mt][0]), "r"(a[mt][1]), "r"(a[mt][2]), "r"(a[mt][3]),
                          "r"(b0), "r"(b1));
                }
            }
        }

        // STS next chunk into the other buffer (it was last read in iteration
        // c-1; the barrier below orders these writes before iter c+1 reads).
        if (c < NCHUNKS - 1) {
            float* nbuf = Xs + ((c + 1) & 1) * XBUF;
            #pragma unroll
            for (int i = 0; i < 8; i++) {
                int f = tid + i * THREADS;
                int row = f >> 3, q = f & 7;
                float* p = nbuf + row * XS_STRIDE + q * 4;
                p[0] = __uint_as_float(f2tf(st[i].x));
                p[1] = __uint_as_float(f2tf(st[i].y));
                p[2] = __uint_as_float(f2tf(st[i].z));
                p[3] = __uint_as_float(f2tf(st[i].w));
            }
        }
        __syncthreads();
    }

    // Epilogue: s[m] = sum_n relu(acc + c[n]) * w2[n]; combine across wn halves.
    // acc frag (m16n8): d0=(g, 2tg), d1=(g, 2tg+1), d2=(g+8, 2tg), d3=(g+8, 2tg+1)
    float* part = Xs;  // reuse (synced after last compute)
    #pragma unroll
    for (int mt = 0; mt < 4; mt++) {
        float sA = 0.0f, sB = 0.0f;
        #pragma unroll
        for (int nt = 0; nt < 8; nt++) {
            int n = wn * 64 + nt * 8 + 2 * tg;
            float c0 = c_s[n],     c1 = c_s[n + 1];
            float w0 = W_tp2[n],   w1 = W_tp2[n + 1];
            sA = fmaf(fmaxf(acc[mt][nt][0] + c0, 0.0f), w0, sA);
            sA = fmaf(fmaxf(acc[mt][nt][1] + c1, 0.0f), w1, sA);
            sB = fmaf(fmaxf(acc[mt][nt][2] + c0, 0.0f), w0, sB);
            sB = fmaf(fmaxf(acc[mt][nt][3] + c1, 0.0f), w1, sB);
        }
        sA += __shfl_xor_sync(0xffffffffu, sA, 1);
        sA += __shfl_xor_sync(0xffffffffu, sA, 2);
        sB += __shfl_xor_sync(0xffffffffu, sB, 1);
        sB += __shfl_xor_sync(0xffffffffu, sB, 2);
        if (tg == 0) {
            int rowA = wm * 64 + mt * 16 + g;
            part[rowA * 2 + wn]       = sA;
            part[(rowA + 8) * 2 + wn] = sB;
        }
    }
    __syncthreads();
    if (tid < BM) {
        int nd = node0 + tid;
        if (nd < N_NODES)
            out[HEAD_OFF + nd] = part[tid * 2] + part[tid * 2 + 1] + b_tp2[0];
    }

    // ---- Blocks 0-2: head FFNs on feats = [node_hidden[0] | h_glob | state]
    if (blockIdx.x < 3) {
        float* feats = Xs + 1024;        // 264 floats (past 'part' region)
        float* hpart = feats + 272;      // 256
        float* hid   = hpart + 256;      // 128

        const int h = blockIdx.x;
        const float* W1 = (h == 0) ? W_hl1 : (h == 1) ? W_in1 : W_ex1;
        const float* b1 = (h == 0) ? b_hl1 : (h == 1) ? b_in1 : b_ex1;
        const float* W2 = (h == 0) ? W_hl2 : (h == 1) ? W_in2 : W_ex2;
        const float* b2 = (h == 0) ? b_hl2 : (h == 1) ? b_in2 : b_ex2;
        const int outd  = (h == 0) ? 4 : (h == 1) ? 5 : 30;
        const int ooff  = (h == 0) ? 0 : (h == 1) ? 4 : 9;

        if (tid < 128) {
            feats[tid]       = X[tid];        // cur = node 0
            feats[128 + tid] = h_glob[tid];
            if (tid < 8) feats[256 + tid] = state[tid];
        }
        __syncthreads();

        const int j = tid & 127, half = tid >> 7;
        const int k0 = half * 132, k1 = k0 + 132;
        float a = 0.0f;
        #pragma unroll 6
        for (int k = k0; k < k1; k++)
            a = fmaf(feats[k], W1[k * HIDDEN + j], a);
        hpart[half * 128 + j] = a;
        __syncthreads();
        if (tid < HIDDEN)
            hid[tid] = fmaxf(hpart[tid] + hpart[128 + tid] + b1[tid], 0.0f);
        __syncthreads();

        if (tid < outd) {
            float o = b2[tid];
            #pragma unroll 8
            for (int k = 0; k < HIDDEN; k++)
                o = fmaf(hid[k], W2[k * outd + tid], o);
            if (h == 2) o += logf(mask[tid]);
            out[ooff + tid] = o;
        }
    }
}

// ---------------------------------------------------------------------------
extern "C" void kernel_launch(void* const* d_in, const int* in_sizes, int n_in,
                              void* d_out, int out_size)
{
    const float* node_hidden = (const float*)d_in[0];
    const float* h_glob      = (const float*)d_in[1];
    const float* state       = (const float*)d_in[2];
    const float* mask        = (const float*)d_in[3];
    const float* W_hl1 = (const float*)d_in[4];
    const float* b_hl1 = (const float*)d_in[5];
    const float* W_hl2 = (const float*)d_in[6];
    const float* b_hl2 = (const float*)d_in[7];
    const float* W_in1 = (const float*)d_in[8];
    const float* b_in1 = (const float*)d_in[9];
    const float* W_in2 = (const float*)d_in[10];
    const float* b_in2 = (const float*)d_in[11];
    const float* W_ex1 = (const float*)d_in[12];
    const float* b_ex1 = (const float*)d_in[13];
    const float* W_ex2 = (const float*)d_in[14];
    const float* b_ex2 = (const float*)d_in[15];
    const float* W_tp1 = (const float*)d_in[16];
    const float* b_tp1 = (const float*)d_in[17];
    const float* W_tp2 = (const float*)d_in[18];
    const float* b_tp2 = (const float*)d_in[19];
    float* out = (float*)d_out;

    const int smem_bytes = (17408 + 2 * XBUF) * 4;  // 143360
    static bool attr_set = false;
    if (!attr_set) {
        cudaFuncSetAttribute(fused_kernel,
                             cudaFuncAttributeMaxDynamicSharedMemorySize,
                             smem_bytes);
        attr_set = true;
    }
    fused_kernel<<<(N_NODES + BM - 1) / BM, THREADS, smem_bytes>>>(
        node_hidden, h_glob, state, mask,
        W_hl1, b_hl1, W_hl2, b_hl2,
        W_in1, b_in1, W_in2, b_in2,
        W_ex1, b_ex1, W_ex2, b_ex2,
        W_tp1, b_tp1, W_tp2, b_tp2, out);
}

// round 14
// speedup vs baseline: 1.1401x; 1.1401x over previous
#include <cuda_runtime.h>
#include <math.h>
#include <stdint.h>

#define HIDDEN   128
#define FEATURE  264
#define N_NODES  400000
#define HEAD_OFF 39     // 4 + 5 + 30 outputs before teleport logits

#define THREADS   256
#define BM        256   // nodes per block (2 independent halves of 128)
#define CHUNK      32   // K per staging chunk
#define WS_STRIDE 136   // 136 % 32 == 8 -> conflict-free B-fragment LDS
#define XS_STRIDE  36   // 36 % 32 == 4 -> conflict-free A-fragment LDS
#define HBUF      (128 * XS_STRIDE)  // 4608 floats: one X buffer for one half
#define NCHUNKS     4   // 128 / 32

__device__ __forceinline__ uint32_t f2tf(float x) {
    uint32_t r;
    asm("cvt.rna.tf32.f32 %0, %1;" : "=r"(r) : "f"(x));
    return r;
}
__device__ __forceinline__ void cp16(uint32_t saddr, const void* gaddr) {
    asm volatile("cp.async.cg.shared.global [%0], [%1], 16;"
                 :: "r"(saddr), "l"(gaddr));
}
__device__ __forceinline__ void half_bar(int half) {
    asm volatile("bar.sync %0, 128;" :: "r"(1 + half) : "memory");
}

// ---------------------------------------------------------------------------
// Single fused kernel, 256 threads = 2 decoupled 128-thread halves.
//  Each half: tf32 mma GEMM for 128 nodes (warp tile m64 x n64), own X
//  double-buffer, named-barrier sync -> halves overlap each other's bubbles.
//  W shared in smem, cvt'd to tf32 once. Blocks 0-2 append the head FFNs.
// ---------------------------------------------------------------------------
__global__ void __launch_bounds__(THREADS, 1) fused_kernel(
    const float* __restrict__ X,      const float* __restrict__ h_glob,
    const float* __restrict__ state,  const float* __restrict__ mask,
    const float* __restrict__ W_hl1, const float* __restrict__ b_hl1,
    const float* __restrict__ W_hl2, const float* __restrict__ b_hl2,
    const float* __restrict__ W_in1, const float* __restrict__ b_in1,
    const float* __restrict__ W_in2, const float* __restrict__ b_in2,
    const float* __restrict__ W_ex1, const float* __restrict__ b_ex1,
    const float* __restrict__ W_ex2, const float* __restrict__ b_ex2,
    const float* __restrict__ W_tp1, const float* __restrict__ b_tp1,
    const float* __restrict__ W_tp2, const float* __restrict__ b_tp2,
    float* __restrict__ out)
{
    extern __shared__ float smem[];
    float* Ws = smem;                  // 128 x 136 = 17408 floats
    float* Xs = smem + 17408;          // 2 halves x 2 bufs x 4608 floats

    __shared__ float c_s[HIDDEN];
    __shared__ float cpart[2][HIDDEN];

    const int tid  = threadIdx.x;
    const int lane = tid & 31;
    const int warp = tid >> 5;        // 0..7
    const int half = warp >> 2;       // 0 or 1 (threads 0-127 / 128-255)
    const int hw   = warp & 3;        // warp within half
    const int wm   = hw & 1;          // m group (2 x 64 rows within half)
    const int wn   = hw >> 1;         // n group (2 x 64 cols)
    const int g    = lane >> 2;
    const int tg   = lane & 3;
    const int lt   = tid & 127;       // thread within half
    const int node0 = blockIdx.x * BM;
    const int hnode0 = node0 + half * 128;

    float* Xh = Xs + half * 2 * HBUF;               // this half's 2 buffers
    const uint32_t Ws_b = (uint32_t)__cvta_generic_to_shared(Ws);
    const uint32_t Xh_b = (uint32_t)__cvta_generic_to_shared(Xh);

    // ---- prologue: cp.async W (all threads) + X chunk 0 (per half), 1 group
    #pragma unroll
    for (int i = 0; i < 16; i++) {
        int f = tid + i * THREADS;        // 0..4095
        int row = f >> 5, q = f & 31;
        cp16(Ws_b + (row * WS_STRIDE + q * 4) * 4,
             W_tp1 + (size_t)(128 + row) * HIDDEN + q * 4);
    }
    #pragma unroll
    for (int i = 0; i < 8; i++) {
        int f = lt + i * 128;             // 0..1023
        int row = f >> 3, q = f & 7;
        size_t grow = hnode0 + row; if (grow >= N_NODES) grow = N_NODES - 1;
        cp16(Xh_b + (row * XS_STRIDE + q * 4) * 4,
             X + grow * HIDDEN + q * 4);
    }
    asm volatile("cp.async.commit_group;");

    // ---- c[j] partials (overlap load latency); rows 0..127 L2-broadcast
    {
        int j = tid & 127, hh = tid >> 7;
        float cv = 0.0f;
        int kb = hh * 64;
        #pragma unroll 8
        for (int k = kb; k < kb + 64; k++)
            cv = fmaf(h_glob[k], W_tp1[k * HIDDEN + j], cv);
        if (hh) {
            #pragma unroll
            for (int k = 0; k < 8; k++)
                cv = fmaf(state[k], W_tp1[(256 + k) * HIDDEN + j], cv);
            cv += b_tp1[j];
        }
        cpart[hh][j] = cv;
    }

    asm volatile("cp.async.wait_group 0;");
    __syncthreads();

    // ---- one-time in-place tf32 cvt of W; combine c partials
    {
        float4* wf = (float4*)Ws;
        #pragma unroll
        for (int i = 0; i < 17; i++) {
            float4 v = wf[tid + i * THREADS];
            v.x = __uint_as_float(f2tf(v.x)); v.y = __uint_as_float(f2tf(v.y));
            v.z = __uint_as_float(f2tf(v.z)); v.w = __uint_as_float(f2tf(v.w));
            wf[tid + i * THREADS] = v;
        }
    }
    if (tid < HIDDEN)
        c_s[tid] = cpart[0][tid] + cpart[1][tid];
    __syncthreads();

    float acc[4][8][4];
    #pragma unroll
    for (int mt = 0; mt < 4; mt++)
        #pragma unroll
        for (int nt = 0; nt < 8; nt++)
            #pragma unroll
            for (int r = 0; r < 4; r++) acc[mt][nt][r] = 0.0f;

    // ---- mainloop: per-half pipeline, ONE named barrier per chunk
    #pragma unroll
    for (int c = 0; c < NCHUNKS; c++) {
        if (c > 0) {
            asm volatile("cp.async.wait_group 0;");
            half_bar(half);               // chunk c visible; chunk c-1 reads done
        }
        if (c < NCHUNKS - 1) {
            // prefetch chunk c+1 into the other buffer (overlaps MMA below)
            uint32_t dstb = Xh_b + ((c + 1) & 1) * (HBUF * 4);
            #pragma unroll
            for (int i = 0; i < 8; i++) {
                int f = lt + i * 128;
                int row = f >> 3, q = f & 7;
                size_t grow = hnode0 + row; if (grow >= N_NODES) grow = N_NODES - 1;
                cp16(dstb + (row * XS_STRIDE + q * 4) * 4,
                     X + grow * HIDDEN + (c + 1) * CHUNK + q * 4);
            }
            asm volatile("cp.async.commit_group;");
        }

        const float* buf = Xh + (c & 1) * HBUF;
        #pragma unroll
        for (int ks = 0; ks < 4; ks++) {
            int kt = c * 4 + ks;
            int col = ks * 8 + tg;
            uint32_t a[4][4];
            #pragma unroll
            for (int mt = 0; mt < 4; mt++) {
                int r0 = wm * 64 + mt * 16 + g;     // local row within half
                a[mt][0] = f2tf(buf[r0 * XS_STRIDE + col]);
                a[mt][1] = f2tf(buf[(r0 + 8) * XS_STRIDE + col]);
                a[mt][2] = f2tf(buf[r0 * XS_STRIDE + col + 4]);
                a[mt][3] = f2tf(buf[(r0 + 8) * XS_STRIDE + col + 4]);
            }
            const float* wrow = Ws + (kt * 8 + tg) * WS_STRIDE + wn * 64 + g;
            #pragma unroll
            for (int nt = 0; nt < 8; nt++) {
                uint32_t b0 = __float_as_uint(wrow[nt * 8]);
                uint32_t b1 = __float_as_uint(wrow[4 * WS_STRIDE + nt * 8]);
                #pragma unroll
                for (int mt = 0; mt < 4; mt++) {
                    asm volatile(
                        "mma.sync.aligned.m16n8k8.row.col.f32.tf32.tf32.f32 "
                        "{%0,%1,%2,%3}, {%4,%5,%6,%7}, {%8,%9}, {%0,%1,%2,%3};"
                        : "+f"(acc[mt][nt][0]), "+f"(acc[mt][nt][1]),
                          "+f"(acc[mt][nt][2]), "+f"(acc[mt][nt][3])
                        : "r"(a[mt][0]), "r"(a[mt][1]), "r"(a[mt][2]), "r"(a[mt][3]),
                          "r"(b0), "r"(b1));
                }
            }
        }
    }
    half_bar(half);   // all MMA reads of this half's buffers done

    // ---- epilogue (per half): s[m] = sum_n relu(acc + c[n]) * w2[n]
    // acc frag (m16n8): d0=(g,2tg), d1=(g,2tg+1), d2=(g+8,2tg), d3=(g+8,2tg+1)
    float* part = Xh;   // this half's region, safe after half_bar
    #pragma unroll
    for (int mt = 0; mt < 4; mt++) {
        float sA = 0.0f, sB = 0.0f;
        #pragma unroll
        for (int nt = 0; nt < 8; nt++) {
            int n = wn * 64 + nt * 8 + 2 * tg;
            float c0 = c_s[n],     c1 = c_s[n + 1];
            float w0 = W_tp2[n],   w1 = W_tp2[n + 1];
            sA = fmaf(fmaxf(acc[mt][nt][0] + c0, 0.0f), w0, sA);
            sA = fmaf(fmaxf(acc[mt][nt][1] + c1, 0.0f), w1, sA);
            sB = fmaf(fmaxf(acc[mt][nt][2] + c0, 0.0f), w0, sB);
            sB = fmaf(fmaxf(acc[mt][nt][3] + c1, 0.0f), w1, sB);
        }
        sA += __shfl_xor_sync(0xffffffffu, sA, 1);
        sA += __shfl_xor_sync(0xffffffffu, sA, 2);
        sB += __shfl_xor_sync(0xffffffffu, sB, 1);
        sB += __shfl_xor_sync(0xffffffffu, sB, 2);
        if (tg == 0) {
            int rA = wm * 64 + mt * 16 + g;      // local row within half
            part[rA * 2 + wn]       = sA;
            part[(rA + 8) * 2 + wn] = sB;
        }
    }
    half_bar(half);
    {
        int nd = hnode0 + lt;
        if (nd < N_NODES)
            out[HEAD_OFF + nd] = part[lt * 2] + part[lt * 2 + 1] + b_tp2[0];
    }

    // ---- blocks 0-2: head FFNs on feats = [node_hidden[0] | h_glob | state]
    if (blockIdx.x < 3) {
        __syncthreads();                 // both halves done with Xs
        float* feats = Xs + 2048;
        float* hpart = feats + 272;      // 256
        float* hid   = hpart + 256;      // 128

        const int h = blockIdx.x;
        const float* W1 = (h == 0) ? W_hl1 : (h == 1) ? W_in1 : W_ex1;
        const float* b1 = (h == 0) ? b_hl1 : (h == 1) ? b_in1 : b_ex1;
        const float* W2 = (h == 0) ? W_hl2 : (h == 1) ? W_in2 : W_ex2;
        const float* b2 = (h == 0) ? b_hl2 : (h == 1) ? b_in2 : b_ex2;
        const int outd  = (h == 0) ? 4 : (h == 1) ? 5 : 30;
        const int ooff  = (h == 0) ? 0 : (h == 1) ? 4 : 9;

        if (tid < 128) {
            feats[tid]       = X[tid];        // cur = node 0
            feats[128 + tid] = h_glob[tid];
            if (tid < 8) feats[256 + tid] = state[tid];
        }
        __syncthreads();

        const int j = tid & 127, hh = tid >> 7;
        const int k0 = hh * 132, k1 = k0 + 132;
        float a = 0.0f;
        #pragma unroll 6
        for (int k = k0; k < k1; k++)
            a = fmaf(feats[k], W1[k * HIDDEN + j], a);
        hpart[hh * 128 + j] = a;
        __syncthreads();
        if (tid < HIDDEN)
            hid[tid] = fmaxf(hpart[tid] + hpart[128 + tid] + b1[tid], 0.0f);
        __syncthreads();

        if (tid < outd) {
            float o = b2[tid];
            #pragma unroll 8
            for (int k = 0; k < HIDDEN; k++)
                o = fmaf(hid[k], W2[k * outd + tid], o);
            if (h == 2) o += logf(mask[tid]);
            out[ooff + tid] = o;
        }
    }
}

// ---------------------------------------------------------------------------
extern "C" void kernel_launch(void* const* d_in, const int* in_sizes, int n_in,
                              void* d_out, int out_size)
{
    const float* node_hidden = (const float*)d_in[0];
    const float* h_glob      = (const float*)d_in[1];
    const float* state       = (const float*)d_in[2];
    const float* mask        = (const float*)d_in[3];
    const float* W_hl1 = (const float*)d_in[4];
    const float* b_hl1 = (const float*)d_in[5];
    const float* W_hl2 = (const float*)d_in[6];
    const float* b_hl2 = (const float*)d_in[7];
    const float* W_in1 = (const float*)d_in[8];
    const float* b_in1 = (const float*)d_in[9];
    const float* W_in2 = (const float*)d_in[10];
    const float* b_in2 = (const float*)d_in[11];
    const float* W_ex1 = (const float*)d_in[12];
    const float* b_ex1 = (const float*)d_in[13];
    const float* W_ex2 = (const float*)d_in[14];
    const float* b_ex2 = (const float*)d_in[15];
    const float* W_tp1 = (const float*)d_in[16];
    const float* b_tp1 = (const float*)d_in[17];
    const float* W_tp2 = (const float*)d_in[18];
    const float* b_tp2 = (const float*)d_in[19];
    float* out = (float*)d_out;

    const int smem_bytes = (17408 + 4 * HBUF) * 4;  // 143360
    static bool attr_set = false;
    if (!attr_set) {
        cudaFuncSetAttribute(fused_kernel,
                             cudaFuncAttributeMaxDynamicSharedMemorySize,
                             smem_bytes);
        attr_set = true;
    }
    fused_kernel<<<(N_NODES + BM - 1) / BM, THREADS, smem_bytes>>>(
        node_hidden, h_glob, state, mask,
        W_hl1, b_hl1, W_hl2, b_hl2,
        W_in1, b_in1, W_in2, b_in2,
        W_ex1, b_ex1, W_ex2, b_ex2,
        W_tp1, b_tp1, W_tp2, b_tp2, out);
}